// round 9
// baseline (speedup 1.0000x reference)
#include <cuda_runtime.h>
#include <cuda_fp16.h>
#include <mma.h>
#include <math.h>
#include <stdint.h>

using namespace nvcuda;

#define N_CELLS 16384
#define D_IN    512
#define D_HID   1024
#define D_OUT   512
#define G3H     3072
#define NF      8
#define FS      2048

// ---------------- device scratch (static, allocation-free) ----------------
__device__ float  d_xvec[256];                         // fused bias for MLP1
__device__ __half d_w1t[256 * 1024];                   // [N=256][K=1024]
__device__ __half d_w2t[512 * 256];                    // [N=512][K=256] ([Wa2;-Wg2]^T)
__device__ float  d_bias2[512];                        // ba2 - bg2
__device__ __half d_whh_t[(size_t)G3H * D_HID];        // W_hh^T [3072][1024]
__device__ __half d_wih_t[(size_t)G3H * D_OUT];        // W_ih[:512]^T [3072][512]
__device__ __half d_hid_h[(size_t)N_CELLS * D_HID];    // fp16 hiddens
__device__ __half d_srelu_h[(size_t)N_CELLS * 256];    // fp16 relu acts (a|g)
__device__ float  d_soutput[(size_t)N_CELLS * 512];    // fp32 output = a - g
__device__ __half d_soutput_h[(size_t)N_CELLS * 512];  // fp16 output
__device__ float  d_tension[N_CELLS];
__device__ float  d_ebuf[N_CELLS];
__device__ float  d_gi[(size_t)N_CELLS * G3H];
__device__ float  d_gh[(size_t)N_CELLS * G3H];
__device__ float  d_hpost[(size_t)N_CELLS * D_HID];
__device__ float  d_sumall[NF * D_HID];
__device__ float  d_sumpos[NF * D_HID];
__device__ float  d_sumneg[NF * D_HID];
__device__ float  d_meanp[D_HID];
__device__ float  d_meann[D_HID];
__device__ float  d_F[NF * D_HID];
__device__ float  d_gop[D_HID];
__device__ int    d_cntp[NF];
__device__ int    d_cntn[NF];
__device__ int    d_cnt_tot[2];
__device__ float  d_tsum;
__device__ float  d_sumexp;
__device__ int    d_tmax_i;
__device__ float  d_cout[512];

// ---------------- cp.async helpers ----------------
__device__ __forceinline__ void cp16(uint32_t daddr, const void* src) {
    asm volatile("cp.async.cg.shared.global [%0], [%1], 16;" :: "r"(daddr), "l"(src));
}
__device__ __forceinline__ void cp_commit() {
    asm volatile("cp.async.commit_group;" ::: "memory");
}
template <int N>
__device__ __forceinline__ void cp_wait() {
    asm volatile("cp.async.wait_group %0;" :: "n"(N) : "memory");
}

// ---------------- pipelined fp16 WMMA GEMM, 128x256 block tile ----------------
// C[M x Ntot] = A[M x K] (fp16 row-major) * Bt[Ntot x K] (fp16 K-major)^T
// Block tile 128x256, BK=32, 3-stage cp.async pipeline, 256 threads,
// warp grid 2x4, warp tile 64x64 (acc 4x4), fp32 accumulate, 1 CTA/SM.
// mode bits: 1=relu, 2=+rowv[m]*colv[n], 8=write half Ch, 16=skip fp32 C
#define STAGE_H 15360   // halves per stage: A 128x40 + B 256x40

__global__ void __launch_bounds__(256, 1) gemm_fp16(
    const __half* __restrict__ A, int lda,
    const __half* __restrict__ Bt,
    float* __restrict__ C, __half* __restrict__ Ch, int ldc,
    int K, int mode,
    const float* __restrict__ bias,
    const float* __restrict__ rowv,
    const float* __restrict__ colv)
{
    extern __shared__ __align__(16) char smem_raw[];
    __half* smem = (__half*)smem_raw;
    const uint32_t sbase = (uint32_t)__cvta_generic_to_shared(smem);

    const int tid  = threadIdx.x;
    const int bm   = blockIdx.y * 128;
    const int bn   = blockIdx.x * 256;
    const int warp = tid >> 5;
    const int wr   = warp & 1;   // 2 warp rows of 64
    const int wc   = warp >> 1;  // 4 warp cols of 64

    wmma::fragment<wmma::accumulator, 16, 16, 16, float> acc[4][4];
#pragma unroll
    for (int i = 0; i < 4; i++)
#pragma unroll
        for (int j = 0; j < 4; j++) wmma::fill_fragment(acc[i][j], 0.0f);

    const int arow = tid >> 1;           // 0..127
    const int acol = (tid & 1) << 4;     // 0 or 16 (halves)

#define ISSUE(KT)                                                              \
    {                                                                          \
        uint32_t so = ((KT) % 3) * STAGE_H;                                    \
        int k0 = (KT) << 5;                                                    \
        _Pragma("unroll")                                                      \
        for (int h2 = 0; h2 < 2; h2++) {                                       \
            int cc = acol + h2 * 8;                                            \
            cp16(sbase + (so + arow * 40 + cc) * 2,                            \
                 A + (size_t)(bm + arow) * lda + k0 + cc);                     \
        }                                                                      \
        _Pragma("unroll")                                                      \
        for (int h4 = 0; h4 < 4; h4++) {                                       \
            int cc = h4 * 8;                                                   \
            cp16(sbase + (so + 5120 + tid * 40 + cc) * 2,                      \
                 Bt + (size_t)(bn + tid) * K + k0 + cc);                       \
        }                                                                      \
        cp_commit();                                                           \
    }

#define MMA_TILE(KT)                                                           \
    {                                                                          \
        __half* As = smem + ((KT) % 3) * STAGE_H;                              \
        __half* Bs = As + 5120;                                                \
        _Pragma("unroll")                                                      \
        for (int kk = 0; kk < 32; kk += 16) {                                  \
            wmma::fragment<wmma::matrix_a, 16, 16, 16, __half, wmma::row_major> af[4]; \
            wmma::fragment<wmma::matrix_b, 16, 16, 16, __half, wmma::col_major> bf[4]; \
            _Pragma("unroll")                                                  \
            for (int i = 0; i < 4; i++)                                        \
                wmma::load_matrix_sync(af[i], As + (wr * 64 + i * 16) * 40 + kk, 40); \
            _Pragma("unroll")                                                  \
            for (int j = 0; j < 4; j++)                                        \
                wmma::load_matrix_sync(bf[j], Bs + (wc * 64 + j * 16) * 40 + kk, 40); \
            _Pragma("unroll")                                                  \
            for (int i = 0; i < 4; i++)                                        \
                _Pragma("unroll")                                              \
                for (int j = 0; j < 4; j++)                                    \
                    wmma::mma_sync(acc[i][j], af[i], bf[j], acc[i][j]);        \
        }                                                                      \
    }

    const int nk = K >> 5;
    ISSUE(0)
    ISSUE(1)

    for (int kt = 0; kt < nk - 1; kt++) {
        cp_wait<1>();
        __syncthreads();
        if (kt + 2 < nk) ISSUE(kt + 2)
        MMA_TILE(kt)
    }
    cp_wait<0>();
    __syncthreads();
    MMA_TILE(nk - 1)
#undef ISSUE
#undef MMA_TILE

    // epilogue in four 64-col bands staged through shared (floats, stride 72)
    float* Cs = (float*)smem;
#pragma unroll
    for (int b = 0; b < 4; b++) {
        __syncthreads();
        if (wc == b) {
#pragma unroll
            for (int i = 0; i < 4; i++)
#pragma unroll
                for (int j = 0; j < 4; j++)
                    wmma::store_matrix_sync(Cs + (wr * 64 + i * 16) * 72 + j * 16,
                                            acc[i][j], 72, wmma::mem_row_major);
        }
        __syncthreads();
#pragma unroll
        for (int it = 0; it < 32; it++) {
            int idx = it * 256 + tid;
            int r = idx >> 6, c = idx & 63;
            int gr = bm + r, gc = bn + (b << 6) + c;
            float v = Cs[r * 72 + c] + bias[gc];
            if (mode & 2) v += rowv[gr] * colv[gc];
            if (mode & 1) v = fmaxf(v, 0.0f);
            if (!(mode & 16)) C[(size_t)gr * ldc + gc] = v;
            if (mode & 8)  Ch[(size_t)gr * ldc + gc] = __float2half(v);
        }
    }
}

// ---------------- prep kernels ----------------
__global__ void cvt_half(const float* __restrict__ src, __half* __restrict__ dst) {
    size_t i = (size_t)blockIdx.x * 256 + threadIdx.x;
    float4 v = reinterpret_cast<const float4*>(src)[i];
    __half2* d = reinterpret_cast<__half2*>(dst) + i * 2;
    d[0] = __floats2half2_rn(v.x, v.y);
    d[1] = __floats2half2_rn(v.z, v.w);
}

// dst[c][r] = (half)src[r][c]; src R x Ccols, dst stride R
__global__ void transpose_half(const float* __restrict__ src, __half* __restrict__ dst,
                               int R, int Ccols) {
    __shared__ float tile[32][33];
    int c0 = blockIdx.x * 32, r0 = blockIdx.y * 32;
    int x = threadIdx.x, y = threadIdx.y;   // (32, 8)
#pragma unroll
    for (int i = 0; i < 32; i += 8)
        tile[y + i][x] = src[(size_t)(r0 + y + i) * Ccols + c0 + x];
    __syncthreads();
#pragma unroll
    for (int i = 0; i < 32; i += 8)
        dst[(size_t)(c0 + y + i) * R + r0 + x] = __float2half(tile[x][y + i]);
}

__global__ void w1t_kernel(const float* __restrict__ Wa1, const float* __restrict__ Wg1) {
    int n = blockIdx.y;                         // 0..255
    int k = blockIdx.x * 256 + threadIdx.x;     // 0..1023
    float v = (n < 128) ? Wa1[(size_t)(512 + k) * 128 + n]
                        : Wg1[(size_t)(512 + k) * 128 + (n - 128)];
    d_w1t[n * 1024 + k] = __float2half(v);
}

__global__ void w2t_kernel(const float* __restrict__ Wa2, const float* __restrict__ ba2,
                           const float* __restrict__ Wg2, const float* __restrict__ bg2) {
    int n = blockIdx.y;                // 0..511
    int k = threadIdx.x;               // 0..255
    float v = (k < 128) ? Wa2[(size_t)k * 512 + n] : -Wg2[(size_t)(k - 128) * 512 + n];
    d_w2t[n * 256 + k] = __float2half(v);
    if (k == 0) d_bias2[n] = ba2[n] - bg2[n];
}

__global__ void init_kernel() {
    int t = threadIdx.x;
    d_cout[t] = 0.0f;
    if (t < NF) { d_cntp[t] = 0; d_cntn[t] = 0; }
    if (t == 0) { d_tsum = 0.0f; d_sumexp = 0.0f; d_tmax_i = 0; }
}

__global__ void count_kernel(const int* __restrict__ pos) {
    int i = blockIdx.x * 256 + threadIdx.x;
    int p = pos[i];
    int f = i >> 11;
    if (p > 0) atomicAdd(&d_cntp[f], 1);
    else if (p < 0) atomicAdd(&d_cntn[f], 1);
}

__global__ void prep_kernel(const float* __restrict__ x,
                            const float* __restrict__ Wa1, const float* __restrict__ ba1,
                            const float* __restrict__ Wg1, const float* __restrict__ bg1) {
    int n = threadIdx.x;                  // 0..255
    const float* W = (n < 128) ? Wa1 : Wg1;
    int col = n & 127;
    float s = (n < 128) ? ba1[col] : bg1[col];
    for (int k = 0; k < D_IN; k++) s += x[k] * W[k * 128 + col];
    d_xvec[n] = s;
}

// ---------------- elementwise / reduction kernels ----------------
__global__ void tension_kernel() {
    int row  = blockIdx.x * 8 + (threadIdx.x >> 5);
    int lane = threadIdx.x & 31;
    const float* o = d_soutput + (size_t)row * 512;
    float s = 0.0f;
    for (int c = lane; c < 512; c += 32) { float v = o[c]; s += v * v; }
#pragma unroll
    for (int off = 16; off; off >>= 1) s += __shfl_xor_sync(0xffffffffu, s, off);
    __shared__ float wsum[8];
    __shared__ float wmax[8];
    float t = s * (1.0f / 512.0f);
    if (lane == 0) {
        d_tension[row] = t;
        wsum[threadIdx.x >> 5] = t;
        wmax[threadIdx.x >> 5] = t;
    }
    __syncthreads();
    if (threadIdx.x == 0) {
        float a = 0.0f, m = 0.0f;
        for (int w = 0; w < 8; w++) { a += wsum[w]; m = fmaxf(m, wmax[w]); }
        atomicAdd(&d_tsum, a);
        atomicMax(&d_tmax_i, __float_as_int(m));   // tension >= 0, int cmp ok
    }
}

__global__ void sumexp_kernel() {
    int i = blockIdx.x * 256 + threadIdx.x;
    float tmax = __int_as_float(d_tmax_i);
    float e = expf(d_tension[i] - tmax);
    d_ebuf[i] = e;
    __shared__ float sh[256];
    sh[threadIdx.x] = e;
    __syncthreads();
    for (int s = 128; s; s >>= 1) {
        if (threadIdx.x < s) sh[threadIdx.x] += sh[threadIdx.x + s];
        __syncthreads();
    }
    if (threadIdx.x == 0) atomicAdd(&d_sumexp, sh[0]);
}

__global__ void gru_kernel(const float* __restrict__ hid, const float* __restrict__ wealth) {
    size_t idx = (size_t)blockIdx.x * 256 + threadIdx.x;
    int i = (int)(idx >> 10), j = (int)(idx & 1023);
    size_t b = (size_t)i * G3H + j;
    float gir = d_gi[b],            ghr = d_gh[b];
    float giz = d_gi[b + 1024],     ghz = d_gh[b + 1024];
    float gin = d_gi[b + 2048],     ghn = d_gh[b + 2048];
    float r = 1.0f / (1.0f + expf(-(gir + ghr)));
    float z = 1.0f / (1.0f + expf(-(giz + ghz)));
    float n = tanhf(gin + r * ghn);
    float h = hid[idx];
    float nh = (1.0f - z) * n + z * h;
    float w = wealth[i];
    float mod = 0.9f + 0.1f * fminf(fmaxf(w, 0.1f), 2.0f);
    nh = fminf(fmaxf(nh * mod, -10.0f), 10.0f);
    d_hpost[idx] = nh;
}

__global__ void stats_kernel(const int* __restrict__ pos) {
    int f = blockIdx.x;
    int j = blockIdx.y * 128 + threadIdx.x;
    int base = f * FS;
    float sa = 0.0f, sp = 0.0f, sn = 0.0f;
    for (int r = 0; r < FS; r++) {
        float v = d_hpost[(size_t)(base + r) * D_HID + j];
        int p = pos[base + r];
        sa += v;
        if (p > 0) sp += v; else if (p < 0) sn += v;
    }
    d_sumall[f * D_HID + j] = sa;
    d_sumpos[f * D_HID + j] = sp;
    d_sumneg[f * D_HID + j] = sn;
}

__global__ void statsfinal_kernel() {
    int j = threadIdx.x;           // 0..1023
    int cp = 0, cn = 0;
    for (int f = 0; f < NF; f++) { cp += d_cntp[f]; cn += d_cntn[f]; }
    float sp = 0.0f, sn = 0.0f;
    for (int f = 0; f < NF; f++) { sp += d_sumpos[f * D_HID + j]; sn += d_sumneg[f * D_HID + j]; }
    float mp = sp / (float)max(cp, 1);
    float mn = sn / (float)max(cn, 1);
    d_meanp[j] = mp; d_meann[j] = mn;
    float g = 0.0f;
    for (int f = 0; f < NF; f++) {
        float adj = d_sumall[f * D_HID + j];
        if (cp >= 2) adj += 0.1f * ((float)d_cntp[f] * mp - d_sumpos[f * D_HID + j]);
        if (cn >= 2) adj += 0.1f * ((float)d_cntn[f] * mn - d_sumneg[f * D_HID + j]);
        float F = adj * (1.0f / (float)FS);
        d_F[f * D_HID + j] = F;
        g += F;
    }
    d_gop[j] = g * (1.0f / (float)NF);
    if (j == 0) { d_cnt_tot[0] = cp; d_cnt_tot[1] = cn; }
}

__global__ void final_kernel(const int* __restrict__ pos, const int* __restrict__ step,
                             float* __restrict__ out) {
    size_t idx = (size_t)blockIdx.x * 256 + threadIdx.x;
    int i = (int)(idx >> 10), j = (int)(idx & 1023);
    float h = d_hpost[idx];
    int p = pos[i];
    int cp = d_cnt_tot[0], cn = d_cnt_tot[1];
    if (p > 0 && cp >= 2)      h = 0.9f * h + 0.1f * d_meanp[j];
    else if (p < 0 && cn >= 2) h = 0.9f * h + 0.1f * d_meann[j];
    int f = i >> 11;
    h = 0.85f * h + 0.15f * d_F[f * D_HID + j];
    if (*step > 5 && (i & (FS - 1)) < (FS / 4)) h = 0.85f * h + 0.15f * d_gop[j];
    out[513 + idx] = h;
}

__global__ void wsum_kernel() {
    int r0 = blockIdx.x * 256;
    float inv = 1.0f / d_sumexp;
    int t = threadIdx.x;
    float c0 = 0.0f, c1 = 0.0f;
    for (int r = r0; r < r0 + 256; r++) {
        float w = d_ebuf[r] * inv;
        const float* o = d_soutput + (size_t)r * 512;
        c0 += w * o[t];
        c1 += w * o[t + 256];
    }
    atomicAdd(&d_cout[t], c0);
    atomicAdd(&d_cout[t + 256], c1);
}

__global__ void pred_kernel(const float* __restrict__ Wo, const float* __restrict__ bo,
                            float* __restrict__ out) {
    __shared__ float co[512];
    int t = threadIdx.x;
    co[t] = d_cout[t];
    __syncthreads();
    float s = bo[t];
    for (int k = 0; k < 512; k++) s += co[k] * Wo[k * 512 + t];
    out[t] = s;
    if (t == 0) out[512] = d_tsum * (1.0f / (float)N_CELLS);
}

// ---------------- launch ----------------
extern "C" void kernel_launch(void* const* d_in, const int* in_sizes, int n_in,
                              void* d_out, int out_size) {
    const float* x        = (const float*)d_in[0];
    const float* hiddens  = (const float*)d_in[1];
    const float* wealth   = (const float*)d_in[2];
    const float* Wa1      = (const float*)d_in[3];
    const float* ba1      = (const float*)d_in[4];
    const float* Wa2      = (const float*)d_in[5];
    const float* ba2      = (const float*)d_in[6];
    const float* Wg1      = (const float*)d_in[7];
    const float* bg1      = (const float*)d_in[8];
    const float* Wg2      = (const float*)d_in[9];
    const float* bg2      = (const float*)d_in[10];
    const float* W_ih     = (const float*)d_in[11];
    const float* W_hh     = (const float*)d_in[12];
    const float* b_ih     = (const float*)d_in[13];
    const float* b_hh     = (const float*)d_in[14];
    const float* Wo       = (const float*)d_in[15];
    const float* bo       = (const float*)d_in[16];
    const int*   positions= (const int*)d_in[17];
    const int*   step     = (const int*)d_in[18];
    float* out = (float*)d_out;

    void *p_srelu_h, *p_soutput, *p_soutput_h, *p_w1t, *p_w2t, *p_bias2, *p_xvec;
    void *p_hid_h, *p_whh_t, *p_wih_t, *p_gi, *p_gh, *p_tension;
    cudaGetSymbolAddress(&p_srelu_h,   d_srelu_h);
    cudaGetSymbolAddress(&p_soutput,   d_soutput);
    cudaGetSymbolAddress(&p_soutput_h, d_soutput_h);
    cudaGetSymbolAddress(&p_w1t,       d_w1t);
    cudaGetSymbolAddress(&p_w2t,       d_w2t);
    cudaGetSymbolAddress(&p_bias2,     d_bias2);
    cudaGetSymbolAddress(&p_xvec,      d_xvec);
    cudaGetSymbolAddress(&p_hid_h,     d_hid_h);
    cudaGetSymbolAddress(&p_whh_t,     d_whh_t);
    cudaGetSymbolAddress(&p_wih_t,     d_wih_t);
    cudaGetSymbolAddress(&p_gi,        d_gi);
    cudaGetSymbolAddress(&p_gh,        d_gh);
    cudaGetSymbolAddress(&p_tension,   d_tension);

    const int SMEM_BYTES = 3 * STAGE_H * 2;   // 92160
    cudaFuncSetAttribute(gemm_fp16,
                         cudaFuncAttributeMaxDynamicSharedMemorySize, SMEM_BYTES);

    init_kernel<<<1, 512>>>();                                               // 1
    transpose_half<<<dim3(96, 32), dim3(32, 8)>>>(W_hh, (__half*)p_whh_t, 1024, 3072); // 2
    cvt_half<<<16384, 256>>>(hiddens, (__half*)p_hid_h);                     // 3

    // gh = hiddens @ W_hh + b_hh   [103 GF]  (4th launch -> ncu target)
    gemm_fp16<<<dim3(12, 128), 256, SMEM_BYTES>>>(                           // 4
        (const __half*)p_hid_h, 1024, (const __half*)p_whh_t,
        (float*)p_gh, nullptr, 3072, 1024, 0, b_hh, nullptr, nullptr);

    transpose_half<<<dim3(96, 16), dim3(32, 8)>>>(W_ih, (__half*)p_wih_t, 512, 3072);  // 5
    prep_kernel<<<1, 256>>>(x, Wa1, ba1, Wg1, bg1);                          // 6
    w1t_kernel<<<dim3(4, 256), 256>>>(Wa1, Wg1);                             // 7
    w2t_kernel<<<dim3(1, 512), 256>>>(Wa2, ba2, Wg2, bg2);                   // 8
    count_kernel<<<64, 256>>>(positions);                                    // 9

    // H1 = relu(hid @ W1 + xvec) -> fp16 only
    gemm_fp16<<<dim3(1, 128), 256, SMEM_BYTES>>>(                            // 10
        (const __half*)p_hid_h, 1024, (const __half*)p_w1t,
        nullptr, (__half*)p_srelu_h, 256, 1024, 1 | 8 | 16,
        (const float*)p_xvec, nullptr, nullptr);

    // soutput = H1 @ [Wa2;-Wg2] + bias2 -> fp32 + fp16
    gemm_fp16<<<dim3(2, 128), 256, SMEM_BYTES>>>(                            // 11
        (const __half*)p_srelu_h, 256, (const __half*)p_w2t,
        (float*)p_soutput, (__half*)p_soutput_h, 512, 256, 8,
        (const float*)p_bias2, nullptr, nullptr);

    tension_kernel<<<2048, 256>>>();                                         // 12
    sumexp_kernel<<<64, 256>>>();                                            // 13

    // gi = output @ W_ih[:512] + tension x W_ih[512] + b_ih   [51.5 GF]
    gemm_fp16<<<dim3(12, 128), 256, SMEM_BYTES>>>(                           // 14
        (const __half*)p_soutput_h, 512, (const __half*)p_wih_t,
        (float*)p_gi, nullptr, 3072, 512, 2, b_ih,
        (const float*)p_tension, W_ih + (size_t)512 * 3072);

    gru_kernel<<<65536, 256>>>(hiddens, wealth);                             // 15
    stats_kernel<<<dim3(8, 8), 128>>>(positions);                            // 16
    statsfinal_kernel<<<1, 1024>>>();                                        // 17
    final_kernel<<<65536, 256>>>(positions, step, out);                      // 18
    wsum_kernel<<<64, 256>>>();                                              // 19
    pred_kernel<<<1, 512>>>(Wo, bo, out);                                    // 20
}

// round 10
// speedup vs baseline: 1.2775x; 1.2775x over previous
#include <cuda_runtime.h>
#include <cuda_fp16.h>
#include <mma.h>
#include <math.h>
#include <stdint.h>

using namespace nvcuda;

#define N_CELLS 16384
#define D_IN    512
#define D_HID   1024
#define D_OUT   512
#define G3H     3072
#define NF      8
#define FS      2048

// ---------------- device scratch (static, allocation-free) ----------------
__device__ float  d_xvec[256];                         // fused bias for MLP1
__device__ __half d_w1t[256 * 1024];                   // [N=256][K=1024]
__device__ __half d_w2t[512 * 256];                    // [N=512][K=256] ([Wa2;-Wg2]^T)
__device__ float  d_bias2[512];                        // ba2 - bg2
__device__ __half d_whh_t[(size_t)G3H * D_HID];        // W_hh^T [3072][1024]
__device__ __half d_wih_t[(size_t)G3H * D_OUT];        // W_ih[:512]^T [3072][512]
__device__ __half d_hid_h[(size_t)N_CELLS * D_HID];    // fp16 hiddens
__device__ __half d_srelu_h[(size_t)N_CELLS * 256];    // fp16 relu acts (a|g)
__device__ __half d_soutput_h[(size_t)N_CELLS * 512];  // fp16 output = a - g
__device__ float  d_tension[N_CELLS];
__device__ float  d_ebuf[N_CELLS];
__device__ __half d_gi_h[(size_t)N_CELLS * G3H];       // fp16 gi preacts
__device__ __half d_gh_h[(size_t)N_CELLS * G3H];       // fp16 gh preacts
__device__ float  d_hpost[(size_t)N_CELLS * D_HID];
__device__ float  d_sumall[NF * D_HID];
__device__ float  d_sumpos[NF * D_HID];
__device__ float  d_sumneg[NF * D_HID];
__device__ float  d_meanp[D_HID];
__device__ float  d_meann[D_HID];
__device__ float  d_F[NF * D_HID];
__device__ float  d_gop[D_HID];
__device__ int    d_cntp[NF];
__device__ int    d_cntn[NF];
__device__ int    d_cnt_tot[2];
__device__ float  d_tsum;
__device__ float  d_sumexp;
__device__ int    d_tmax_i;
__device__ float  d_cout[512];

// ---------------- cp.async helpers ----------------
__device__ __forceinline__ void cp16(uint32_t daddr, const void* src) {
    asm volatile("cp.async.cg.shared.global [%0], [%1], 16;" :: "r"(daddr), "l"(src));
}
__device__ __forceinline__ void cp_commit() {
    asm volatile("cp.async.commit_group;" ::: "memory");
}
template <int N>
__device__ __forceinline__ void cp_wait() {
    asm volatile("cp.async.wait_group %0;" :: "n"(N) : "memory");
}

// ---------------- pipelined fp16 WMMA GEMM (round-6 proven config) ---------
// C[M x Ntot] = A[M x K] (fp16, row-major) * Bt[Ntot x K] (fp16, K-major)^T
// Block tile 128x128, BK=32, 3-stage cp.async pipeline, 256 threads,
// warp grid 2x4 (warp tile 64x32), fp32 accumulate, 2 CTAs/SM.
// modes: 1 = relu, 2 = + rowv[m]*colv[n], 8 = write half to Ch, 16 = skip fp32 C
#define STAGE_H 10240   // halves per stage: A 128x40 + B 128x40

__global__ void __launch_bounds__(256, 2) gemm_fp16(
    const __half* __restrict__ A, int lda,
    const __half* __restrict__ Bt,
    float* __restrict__ C, __half* __restrict__ Ch, int ldc,
    int K, int mode,
    const float* __restrict__ bias,
    const float* __restrict__ rowv,
    const float* __restrict__ colv)
{
    extern __shared__ __align__(16) char smem_raw[];
    __half* smem = (__half*)smem_raw;
    const uint32_t sbase = (uint32_t)__cvta_generic_to_shared(smem);

    const int tid  = threadIdx.x;
    const int bm   = blockIdx.y * 128;
    const int bn   = blockIdx.x * 128;
    const int warp = tid >> 5;
    const int wr   = warp & 1;   // 2 warp rows of 64
    const int wc   = warp >> 1;  // 4 warp cols of 32

    wmma::fragment<wmma::accumulator, 16, 16, 16, float> acc[4][2];
#pragma unroll
    for (int i = 0; i < 4; i++)
#pragma unroll
        for (int j = 0; j < 2; j++) wmma::fill_fragment(acc[i][j], 0.0f);

    const int crow = tid >> 1;           // 0..127
    const int ccol = (tid & 1) << 4;     // 0 or 16 (halves)

#define ISSUE(KT)                                                              \
    {                                                                          \
        uint32_t so = ((KT) % 3) * STAGE_H;                                    \
        int k0 = (KT) << 5;                                                    \
        _Pragma("unroll")                                                      \
        for (int h2 = 0; h2 < 2; h2++) {                                       \
            int cc = ccol + h2 * 8;                                            \
            cp16(sbase + (so + crow * 40 + cc) * 2,                            \
                 A + (size_t)(bm + crow) * lda + k0 + cc);                     \
            cp16(sbase + (so + 5120 + crow * 40 + cc) * 2,                     \
                 Bt + (size_t)(bn + crow) * K + k0 + cc);                      \
        }                                                                      \
        cp_commit();                                                           \
    }

#define MMA_TILE(KT)                                                           \
    {                                                                          \
        __half* As = smem + ((KT) % 3) * STAGE_H;                              \
        __half* Bs = As + 5120;                                                \
        _Pragma("unroll")                                                      \
        for (int kk = 0; kk < 32; kk += 16) {                                  \
            wmma::fragment<wmma::matrix_a, 16, 16, 16, __half, wmma::row_major> af[4]; \
            wmma::fragment<wmma::matrix_b, 16, 16, 16, __half, wmma::col_major> bf[2]; \
            _Pragma("unroll")                                                  \
            for (int i = 0; i < 4; i++)                                        \
                wmma::load_matrix_sync(af[i], As + (wr * 64 + i * 16) * 40 + kk, 40); \
            _Pragma("unroll")                                                  \
            for (int j = 0; j < 2; j++)                                        \
                wmma::load_matrix_sync(bf[j], Bs + (wc * 32 + j * 16) * 40 + kk, 40); \
            _Pragma("unroll")                                                  \
            for (int i = 0; i < 4; i++)                                        \
                _Pragma("unroll")                                              \
                for (int j = 0; j < 2; j++)                                    \
                    wmma::mma_sync(acc[i][j], af[i], bf[j], acc[i][j]);        \
        }                                                                      \
    }

    const int nk = K >> 5;
    ISSUE(0)
    ISSUE(1)

    for (int kt = 0; kt < nk - 1; kt++) {
        cp_wait<1>();
        __syncthreads();
        if (kt + 2 < nk) ISSUE(kt + 2)
        MMA_TILE(kt)
    }
    cp_wait<0>();
    __syncthreads();
    MMA_TILE(nk - 1)
#undef ISSUE
#undef MMA_TILE

    // epilogue in two 64-col halves staged through shared (floats, stride 72)
    float* Cs = (float*)smem;
#pragma unroll
    for (int h = 0; h < 2; h++) {
        __syncthreads();
        if ((wc >> 1) == h) {
            const int lc = (wc & 1) << 5;
#pragma unroll
            for (int i = 0; i < 4; i++)
#pragma unroll
                for (int j = 0; j < 2; j++)
                    wmma::store_matrix_sync(Cs + (wr * 64 + i * 16) * 72 + lc + j * 16,
                                            acc[i][j], 72, wmma::mem_row_major);
        }
        __syncthreads();
#pragma unroll
        for (int it = 0; it < 32; it++) {
            int idx = it * 256 + tid;
            int r = idx >> 6, c = idx & 63;
            int gr = bm + r, gc = bn + (h << 6) + c;
            float v = Cs[r * 72 + c] + bias[gc];
            if (mode & 2) v += rowv[gr] * colv[gc];
            if (mode & 1) v = fmaxf(v, 0.0f);
            if (!(mode & 16)) C[(size_t)gr * ldc + gc] = v;
            if (mode & 8)  Ch[(size_t)gr * ldc + gc] = __float2half(v);
        }
    }
}

// ---------------- prep kernels ----------------
__global__ void cvt_half(const float* __restrict__ src, __half* __restrict__ dst) {
    size_t i = (size_t)blockIdx.x * 256 + threadIdx.x;
    float4 v = reinterpret_cast<const float4*>(src)[i];
    __half2* d = reinterpret_cast<__half2*>(dst) + i * 2;
    d[0] = __floats2half2_rn(v.x, v.y);
    d[1] = __floats2half2_rn(v.z, v.w);
}

// dst[c][r] = (half)src[r][c]; src R x Ccols, dst stride R
__global__ void transpose_half(const float* __restrict__ src, __half* __restrict__ dst,
                               int R, int Ccols) {
    __shared__ float tile[32][33];
    int c0 = blockIdx.x * 32, r0 = blockIdx.y * 32;
    int x = threadIdx.x, y = threadIdx.y;   // (32, 8)
#pragma unroll
    for (int i = 0; i < 32; i += 8)
        tile[y + i][x] = src[(size_t)(r0 + y + i) * Ccols + c0 + x];
    __syncthreads();
#pragma unroll
    for (int i = 0; i < 32; i += 8)
        dst[(size_t)(c0 + y + i) * R + r0 + x] = __float2half(tile[x][y + i]);
}

__global__ void w1t_kernel(const float* __restrict__ Wa1, const float* __restrict__ Wg1) {
    int n = blockIdx.y;                         // 0..255
    int k = blockIdx.x * 256 + threadIdx.x;     // 0..1023
    float v = (n < 128) ? Wa1[(size_t)(512 + k) * 128 + n]
                        : Wg1[(size_t)(512 + k) * 128 + (n - 128)];
    d_w1t[n * 1024 + k] = __float2half(v);
}

__global__ void w2t_kernel(const float* __restrict__ Wa2, const float* __restrict__ ba2,
                           const float* __restrict__ Wg2, const float* __restrict__ bg2) {
    int n = blockIdx.y;                // 0..511
    int k = threadIdx.x;               // 0..255
    float v = (k < 128) ? Wa2[(size_t)k * 512 + n] : -Wg2[(size_t)(k - 128) * 512 + n];
    d_w2t[n * 256 + k] = __float2half(v);
    if (k == 0) d_bias2[n] = ba2[n] - bg2[n];
}

__global__ void init_kernel() {
    int t = threadIdx.x;
    d_cout[t] = 0.0f;
    if (t < NF) { d_cntp[t] = 0; d_cntn[t] = 0; }
    if (t == 0) { d_tsum = 0.0f; d_sumexp = 0.0f; d_tmax_i = 0; }
}

__global__ void count_kernel(const int* __restrict__ pos) {
    int i = blockIdx.x * 256 + threadIdx.x;
    int p = pos[i];
    int f = i >> 11;
    if (p > 0) atomicAdd(&d_cntp[f], 1);
    else if (p < 0) atomicAdd(&d_cntn[f], 1);
}

__global__ void prep_kernel(const float* __restrict__ x,
                            const float* __restrict__ Wa1, const float* __restrict__ ba1,
                            const float* __restrict__ Wg1, const float* __restrict__ bg1) {
    int n = threadIdx.x;                  // 0..255
    const float* W = (n < 128) ? Wa1 : Wg1;
    int col = n & 127;
    float s = (n < 128) ? ba1[col] : bg1[col];
    for (int k = 0; k < D_IN; k++) s += x[k] * W[k * 128 + col];
    d_xvec[n] = s;
}

// ---------------- elementwise / reduction kernels ----------------
// tension from fp16 soutput (fp32 accumulate)
__global__ void tension_kernel() {
    int row  = blockIdx.x * 8 + (threadIdx.x >> 5);
    int lane = threadIdx.x & 31;
    const __half2* o = reinterpret_cast<const __half2*>(d_soutput_h + (size_t)row * 512);
    float s = 0.0f;
    for (int c = lane; c < 256; c += 32) {
        float2 v = __half22float2(o[c]);
        s += v.x * v.x + v.y * v.y;
    }
#pragma unroll
    for (int off = 16; off; off >>= 1) s += __shfl_xor_sync(0xffffffffu, s, off);
    __shared__ float wsum[8];
    __shared__ float wmax[8];
    float t = s * (1.0f / 512.0f);
    if (lane == 0) {
        d_tension[row] = t;
        wsum[threadIdx.x >> 5] = t;
        wmax[threadIdx.x >> 5] = t;
    }
    __syncthreads();
    if (threadIdx.x == 0) {
        float a = 0.0f, m = 0.0f;
        for (int w = 0; w < 8; w++) { a += wsum[w]; m = fmaxf(m, wmax[w]); }
        atomicAdd(&d_tsum, a);
        atomicMax(&d_tmax_i, __float_as_int(m));   // tension >= 0, int cmp ok
    }
}

__global__ void sumexp_kernel() {
    int i = blockIdx.x * 256 + threadIdx.x;
    float tmax = __int_as_float(d_tmax_i);
    float e = expf(d_tension[i] - tmax);
    d_ebuf[i] = e;
    __shared__ float sh[256];
    sh[threadIdx.x] = e;
    __syncthreads();
    for (int s = 128; s; s >>= 1) {
        if (threadIdx.x < s) sh[threadIdx.x] += sh[threadIdx.x + s];
        __syncthreads();
    }
    if (threadIdx.x == 0) atomicAdd(&d_sumexp, sh[0]);
}

// GRU combine + wealth mod + clip (reads fp16 preacts)
__global__ void gru_kernel(const float* __restrict__ hid, const float* __restrict__ wealth) {
    size_t idx = (size_t)blockIdx.x * 256 + threadIdx.x;
    int i = (int)(idx >> 10), j = (int)(idx & 1023);
    size_t b = (size_t)i * G3H + j;
    float gir = __half2float(d_gi_h[b]),        ghr = __half2float(d_gh_h[b]);
    float giz = __half2float(d_gi_h[b + 1024]), ghz = __half2float(d_gh_h[b + 1024]);
    float gin = __half2float(d_gi_h[b + 2048]), ghn = __half2float(d_gh_h[b + 2048]);
    float r = 1.0f / (1.0f + expf(-(gir + ghr)));
    float z = 1.0f / (1.0f + expf(-(giz + ghz)));
    float n = tanhf(gin + r * ghn);
    float h = hid[idx];
    float nh = (1.0f - z) * n + z * h;
    float w = wealth[i];
    float mod = 0.9f + 0.1f * fminf(fmaxf(w, 0.1f), 2.0f);
    nh = fminf(fmaxf(nh * mod, -10.0f), 10.0f);
    d_hpost[idx] = nh;
}

__global__ void stats_kernel(const int* __restrict__ pos) {
    int f = blockIdx.x;
    int j = blockIdx.y * 128 + threadIdx.x;
    int base = f * FS;
    float sa = 0.0f, sp = 0.0f, sn = 0.0f;
    for (int r = 0; r < FS; r++) {
        float v = d_hpost[(size_t)(base + r) * D_HID + j];
        int p = pos[base + r];
        sa += v;
        if (p > 0) sp += v; else if (p < 0) sn += v;
    }
    d_sumall[f * D_HID + j] = sa;
    d_sumpos[f * D_HID + j] = sp;
    d_sumneg[f * D_HID + j] = sn;
}

__global__ void statsfinal_kernel() {
    int j = threadIdx.x;           // 0..1023
    int cp = 0, cn = 0;
    for (int f = 0; f < NF; f++) { cp += d_cntp[f]; cn += d_cntn[f]; }
    float sp = 0.0f, sn = 0.0f;
    for (int f = 0; f < NF; f++) { sp += d_sumpos[f * D_HID + j]; sn += d_sumneg[f * D_HID + j]; }
    float mp = sp / (float)max(cp, 1);
    float mn = sn / (float)max(cn, 1);
    d_meanp[j] = mp; d_meann[j] = mn;
    float g = 0.0f;
    for (int f = 0; f < NF; f++) {
        float adj = d_sumall[f * D_HID + j];
        if (cp >= 2) adj += 0.1f * ((float)d_cntp[f] * mp - d_sumpos[f * D_HID + j]);
        if (cn >= 2) adj += 0.1f * ((float)d_cntn[f] * mn - d_sumneg[f * D_HID + j]);
        float F = adj * (1.0f / (float)FS);
        d_F[f * D_HID + j] = F;
        g += F;
    }
    d_gop[j] = g * (1.0f / (float)NF);
    if (j == 0) { d_cnt_tot[0] = cp; d_cnt_tot[1] = cn; }
}

__global__ void final_kernel(const int* __restrict__ pos, const int* __restrict__ step,
                             float* __restrict__ out) {
    size_t idx = (size_t)blockIdx.x * 256 + threadIdx.x;
    int i = (int)(idx >> 10), j = (int)(idx & 1023);
    float h = d_hpost[idx];
    int p = pos[i];
    int cp = d_cnt_tot[0], cn = d_cnt_tot[1];
    if (p > 0 && cp >= 2)      h = 0.9f * h + 0.1f * d_meanp[j];
    else if (p < 0 && cn >= 2) h = 0.9f * h + 0.1f * d_meann[j];
    int f = i >> 11;
    h = 0.85f * h + 0.15f * d_F[f * D_HID + j];
    if (*step > 5 && (i & (FS - 1)) < (FS / 4)) h = 0.85f * h + 0.15f * d_gop[j];
    out[513 + idx] = h;
}

// combined_out from fp16 soutput (fp32 accumulate)
__global__ void wsum_kernel() {
    int r0 = blockIdx.x * 256;
    float inv = 1.0f / d_sumexp;
    int t = threadIdx.x;
    float c0 = 0.0f, c1 = 0.0f;
    for (int r = r0; r < r0 + 256; r++) {
        float w = d_ebuf[r] * inv;
        const __half* o = d_soutput_h + (size_t)r * 512;
        c0 += w * __half2float(o[t]);
        c1 += w * __half2float(o[t + 256]);
    }
    atomicAdd(&d_cout[t], c0);
    atomicAdd(&d_cout[t + 256], c1);
}

__global__ void pred_kernel(const float* __restrict__ Wo, const float* __restrict__ bo,
                            float* __restrict__ out) {
    __shared__ float co[512];
    int t = threadIdx.x;
    co[t] = d_cout[t];
    __syncthreads();
    float s = bo[t];
    for (int k = 0; k < 512; k++) s += co[k] * Wo[k * 512 + t];
    out[t] = s;
    if (t == 0) out[512] = d_tsum * (1.0f / (float)N_CELLS);
}

// ---------------- launch ----------------
extern "C" void kernel_launch(void* const* d_in, const int* in_sizes, int n_in,
                              void* d_out, int out_size) {
    const float* x        = (const float*)d_in[0];
    const float* hiddens  = (const float*)d_in[1];
    const float* wealth   = (const float*)d_in[2];
    const float* Wa1      = (const float*)d_in[3];
    const float* ba1      = (const float*)d_in[4];
    const float* Wa2      = (const float*)d_in[5];
    const float* ba2      = (const float*)d_in[6];
    const float* Wg1      = (const float*)d_in[7];
    const float* bg1      = (const float*)d_in[8];
    const float* Wg2      = (const float*)d_in[9];
    const float* bg2      = (const float*)d_in[10];
    const float* W_ih     = (const float*)d_in[11];
    const float* W_hh     = (const float*)d_in[12];
    const float* b_ih     = (const float*)d_in[13];
    const float* b_hh     = (const float*)d_in[14];
    const float* Wo       = (const float*)d_in[15];
    const float* bo       = (const float*)d_in[16];
    const int*   positions= (const int*)d_in[17];
    const int*   step     = (const int*)d_in[18];
    float* out = (float*)d_out;

    void *p_srelu_h, *p_soutput_h, *p_w1t, *p_w2t, *p_bias2, *p_xvec;
    void *p_hid_h, *p_whh_t, *p_wih_t, *p_gi_h, *p_gh_h, *p_tension;
    cudaGetSymbolAddress(&p_srelu_h,   d_srelu_h);
    cudaGetSymbolAddress(&p_soutput_h, d_soutput_h);
    cudaGetSymbolAddress(&p_w1t,       d_w1t);
    cudaGetSymbolAddress(&p_w2t,       d_w2t);
    cudaGetSymbolAddress(&p_bias2,     d_bias2);
    cudaGetSymbolAddress(&p_xvec,      d_xvec);
    cudaGetSymbolAddress(&p_hid_h,     d_hid_h);
    cudaGetSymbolAddress(&p_whh_t,     d_whh_t);
    cudaGetSymbolAddress(&p_wih_t,     d_wih_t);
    cudaGetSymbolAddress(&p_gi_h,      d_gi_h);
    cudaGetSymbolAddress(&p_gh_h,      d_gh_h);
    cudaGetSymbolAddress(&p_tension,   d_tension);

    const int SMEM_BYTES = 3 * STAGE_H * 2;   // 61440
    cudaFuncSetAttribute(gemm_fp16,
                         cudaFuncAttributeMaxDynamicSharedMemorySize, SMEM_BYTES);

    init_kernel<<<1, 512>>>();                                               // 1
    transpose_half<<<dim3(96, 32), dim3(32, 8)>>>(W_hh, (__half*)p_whh_t, 1024, 3072); // 2
    cvt_half<<<16384, 256>>>(hiddens, (__half*)p_hid_h);                     // 3

    // gh = hiddens @ W_hh + b_hh   [103 GF] -> fp16   (4th launch for ncu)
    gemm_fp16<<<dim3(24, 128), 256, SMEM_BYTES>>>(                           // 4
        (const __half*)p_hid_h, 1024, (const __half*)p_whh_t,
        nullptr, (__half*)p_gh_h, 3072, 1024, 8 | 16, b_hh, nullptr, nullptr);

    transpose_half<<<dim3(96, 16), dim3(32, 8)>>>(W_ih, (__half*)p_wih_t, 512, 3072);  // 5
    prep_kernel<<<1, 256>>>(x, Wa1, ba1, Wg1, bg1);                          // 6
    w1t_kernel<<<dim3(4, 256), 256>>>(Wa1, Wg1);                             // 7
    w2t_kernel<<<dim3(1, 512), 256>>>(Wa2, ba2, Wg2, bg2);                   // 8
    count_kernel<<<64, 256>>>(positions);                                    // 9

    // H1 = relu(hid @ W1 + xvec) -> fp16 only
    gemm_fp16<<<dim3(2, 128), 256, SMEM_BYTES>>>(                            // 10
        (const __half*)p_hid_h, 1024, (const __half*)p_w1t,
        nullptr, (__half*)p_srelu_h, 256, 1024, 1 | 8 | 16,
        (const float*)p_xvec, nullptr, nullptr);

    // soutput = H1 @ [Wa2;-Wg2] + bias2 -> fp16 only
    gemm_fp16<<<dim3(4, 128), 256, SMEM_BYTES>>>(                            // 11
        (const __half*)p_srelu_h, 256, (const __half*)p_w2t,
        nullptr, (__half*)p_soutput_h, 512, 256, 8 | 16,
        (const float*)p_bias2, nullptr, nullptr);

    tension_kernel<<<2048, 256>>>();                                         // 12
    sumexp_kernel<<<64, 256>>>();                                            // 13

    // gi = output @ W_ih[:512] + tension x W_ih[512] + b_ih  [51.5 GF] -> fp16
    gemm_fp16<<<dim3(24, 128), 256, SMEM_BYTES>>>(                           // 14
        (const __half*)p_soutput_h, 512, (const __half*)p_wih_t,
        nullptr, (__half*)p_gi_h, 3072, 512, 2 | 8 | 16, b_ih,
        (const float*)p_tension, W_ih + (size_t)512 * 3072);

    gru_kernel<<<65536, 256>>>(hiddens, wealth);                             // 15
    stats_kernel<<<dim3(8, 8), 128>>>(positions);                            // 16
    statsfinal_kernel<<<1, 1024>>>();                                        // 17
    final_kernel<<<65536, 256>>>(positions, step, out);                      // 18
    wsum_kernel<<<64, 256>>>();                                              // 19
    pred_kernel<<<1, 512>>>(Wo, bo, out);                                    // 20
}